// round 15
// baseline (speedup 1.0000x reference)
#include <cuda_runtime.h>
#include <cuda_bf16.h>
#include <cstdint>

// Problem constants
#define BB   16
#define NN   8192
#define CIN  3
#define HID  64
#define DD   256
#define KK   4
#define GHID 128
#define DOUT 128
#define TILE 128
#define NT   (NN / TILE)            // 64 tiles
#define SLOTS (NT * BB)             // 1024 (tile,b) slots per branch
#define BLKS_PER_KB 74
#define PBLOCKS (BLKS_PER_KB * KK)  // 296 = 2 CTAs x 148 SMs

#define RSTRIDE 72                  // padded row stride in bf16 units (144 B)

// dynamic smem layout (bytes)
#define OFF_W2HI 0                      // [DD][RSTRIDE] bf16 = 36864
#define OFF_W2LO 36864                  // 36864
#define OFF_HHI  73728                  // [TILE][RSTRIDE] bf16 = 18432
#define OFF_HLO  92160                  // 18432
#define OFF_X0   110592                 // [TILE] float
#define OFF_X1   111104
#define OFF_X2   111616
#define OFF_W1   112128                 // [CIN*HID] float
#define OFF_B1   112896                 // [HID] float
#define K2_SMEM  113152                 // 110.5 KB -> 2 CTAs = 221 KB/SM

// ---------------- device scratch (static, no allocations) ----------------
__device__ int      g_cnt[BB * KK];
__device__ int      g_idx[BB * KK * NN];       // per (b,k) index lists
__device__ unsigned g_maxu[BB * DD];           // flipped-float max slots

// ---------------- helpers ----------------
__device__ __forceinline__ float gelu_exact(float x) {
    return 0.5f * x * (1.0f + erff(x * 0.7071067811865476f));
}

// Fast exact-GELU for small |v| (Taylor of erf, rel err < 1.3e-6 for |v|<=0.5)
__device__ __forceinline__ float gelu_fast(float v) {
    float s = v * v;
    if (s > 0.25f) {
        return 0.5f * v * (1.0f + erff(v * 0.7071067811865476f));
    }
    float p = fmaf(s, -1.0f / 336.0f, 1.0f / 40.0f);
    p = fmaf(s, p, -1.0f / 6.0f);
    p = fmaf(s, p, 1.0f);
    return fmaf(0.3989422804014327f * v * v, p, 0.5f * v);
}

__device__ __forceinline__ unsigned pack_bf16(float a, float b) {
    unsigned short ua = __bfloat16_as_ushort(__float2bfloat16(a));
    unsigned short ub = __bfloat16_as_ushort(__float2bfloat16(b));
    return (unsigned)ua | ((unsigned)ub << 16);
}

// m16n8k16 row.col bf16 MMA, fp32 accumulate (standard sm_80+ fragment layout)
__device__ __forceinline__ void mma_bf16(float* c,
                                         unsigned a0, unsigned a1,
                                         unsigned a2, unsigned a3,
                                         unsigned b0, unsigned b1) {
    asm volatile(
        "mma.sync.aligned.m16n8k16.row.col.f32.bf16.bf16.f32 "
        "{%0,%1,%2,%3}, {%4,%5,%6,%7}, {%8,%9}, {%0,%1,%2,%3};\n"
        : "+f"(c[0]), "+f"(c[1]), "+f"(c[2]), "+f"(c[3])
        : "r"(a0), "r"(a1), "r"(a2), "r"(a3), "r"(b0), "r"(b1));
}

// order-preserving float -> uint mapping (for exact atomic max)
__device__ __forceinline__ unsigned flip_f32(float f) {
    unsigned u = __float_as_uint(f);
    return (u & 0x80000000u) ? ~u : (u | 0x80000000u);
}
__device__ __forceinline__ float unflip_f32(unsigned e) {
    unsigned u = (e & 0x80000000u) ? (e ^ 0x80000000u) : ~e;
    return __uint_as_float(u);
}

// ---------------- K0: reset scratch ----------------
__global__ void k0_init() {
    int i = blockIdx.x * 256 + threadIdx.x;
    if (i < BB * KK) g_cnt[i] = 0;
    if (i < BB * DD) g_maxu[i] = 0u;   // below all finite flipped floats
}

// ---------------- K1: argmax classify + compaction ----------------
__global__ void k1_classify(const float* __restrict__ lab) {
    __shared__ int scnt[KK];
    __shared__ int sbase[KK];
    int t   = threadIdx.x;
    int gid = blockIdx.x * 256 + t;
    int b   = gid / NN;
    int n   = gid % NN;

    if (t < KK) scnt[t] = 0;
    __syncthreads();

    const float* lb = lab + (size_t)b * KK * NN + n;
    float l0 = lb[0], l1 = lb[NN], l2 = lb[2 * NN], l3 = lb[3 * NN];
    int k = 0; float best = l0;
    if (l1 > best) { best = l1; k = 1; }
    if (l2 > best) { best = l2; k = 2; }
    if (l3 > best) { best = l3; k = 3; }

    int pos = atomicAdd(&scnt[k], 1);
    __syncthreads();
    if (t < KK) sbase[t] = atomicAdd(&g_cnt[b * KK + t], scnt[t]);
    __syncthreads();
    g_idx[(b * KK + k) * NN + sbase[k] + pos] = n;
}

// ---------------- K2: persistent, branch-pinned, TENSOR phase 2 ----------------
// 296 blocks (2 CTAs x 148 SMs), 256 threads, kb fixed per block.
// TILE=128 points per item (half the items of R14 -> half the per-item fixed
// cost), idx staging dropped (one fewer barrier per item). Phase-2 fragment
// machinery identical to R14: 3-split bf16 m16n8k16 MMA, RSTRIDE=72 padding,
// masked fold, butterfly, atomicMax.
__global__ __launch_bounds__(256, 2)
void k2_main(const float* __restrict__ x,
             const float* __restrict__ W1, const float* __restrict__ b1,
             const float* __restrict__ W2g, const float* __restrict__ b2) {
    extern __shared__ __align__(16) char smem[];
    __nv_bfloat16* w2hi = reinterpret_cast<__nv_bfloat16*>(smem + OFF_W2HI);
    __nv_bfloat16* w2lo = reinterpret_cast<__nv_bfloat16*>(smem + OFF_W2LO);
    float* sh_x0 = reinterpret_cast<float*>(smem + OFF_X0);
    float* sh_x1 = reinterpret_cast<float*>(smem + OFF_X1);
    float* sh_x2 = reinterpret_cast<float*>(smem + OFF_X2);
    float* sh_w1 = reinterpret_cast<float*>(smem + OFF_W1);
    float* sh_b1 = reinterpret_cast<float*>(smem + OFF_B1);

    const int t     = threadIdx.x;
    const int kb    = blockIdx.x & 3;
    const int slot0 = blockIdx.x >> 2;       // 0..73
    const int w     = t >> 5;                // warp 0..7
    const int lane  = t & 31;
    const int lq    = lane >> 2;             // 0..7 (row group / n col)
    const int lr    = lane & 3;              // 0..3 (k/col pair select)
    const int d0    = w * 32;

    // ---- once per block: W1/b1 + W2 split->bf16, transposed [d][k] ----
    {
        const int d = t;                     // 0..255
        #pragma unroll 8
        for (int k = 0; k < HID; k++) {
            float wv = W2g[((size_t)kb * HID + k) * DD + d];
            __nv_bfloat16 hi = __float2bfloat16(wv);
            float lo = wv - __bfloat162float(hi);
            w2hi[d * RSTRIDE + k] = hi;
            w2lo[d * RSTRIDE + k] = __float2bfloat16(lo);
        }
        if (t < CIN * HID) sh_w1[t] = W1[kb * CIN * HID + t];
        if (t < HID)       sh_b1[t] = b1[kb * HID + t];
    }
    __syncthreads();

    for (int it = slot0; it < SLOTS; it += BLKS_PER_KB) {
        const int tile = it >> 4;            // 0..63
        const int b    = it & 15;

        const int cnt   = g_cnt[b * KK + kb];
        const int start = tile * TILE;
        if (start >= cnt) continue;          // block-uniform branch
        const int npts = min(TILE, cnt - start);

        __syncthreads();   // previous item's phase-2 reads done before overwrite

        // direct gather: idx -> register -> x into smem (no idx staging)
        if (t < TILE && t < npts) {
            int n = g_idx[(b * KK + kb) * NN + start + t];
            const float* xb = x + (size_t)b * CIN * NN;
            sh_x0[t] = xb[n];
            sh_x1[t] = xb[NN + n];
            sh_x2[t] = xb[2 * NN + n];
        }
        __syncthreads();

        // ---- phase 1: pt = t&127, jhalf = t>>7 covers 32 j's; bf16 split
        {
            const int pt = t & 127;
            const int j0 = (t >> 7) * 32;
            unsigned* hhi = reinterpret_cast<unsigned*>(smem + OFF_HHI) + (pt * RSTRIDE + j0) / 2;
            unsigned* hlo = reinterpret_cast<unsigned*>(smem + OFF_HLO) + (pt * RSTRIDE + j0) / 2;
            if (pt < npts) {
                float x0 = sh_x0[pt], x1 = sh_x1[pt], x2 = sh_x2[pt];
                #pragma unroll
                for (int p = 0; p < 16; p++) {
                    int ja = j0 + 2 * p, jb = ja + 1;
                    float va = fmaf(x0, sh_w1[ja],
                               fmaf(x1, sh_w1[HID + ja],
                               fmaf(x2, sh_w1[2 * HID + ja], sh_b1[ja])));
                    float vb = fmaf(x0, sh_w1[jb],
                               fmaf(x1, sh_w1[HID + jb],
                               fmaf(x2, sh_w1[2 * HID + jb], sh_b1[jb])));
                    va = gelu_fast(va);
                    vb = gelu_fast(vb);
                    __nv_bfloat16 ha = __float2bfloat16(va);
                    __nv_bfloat16 hb = __float2bfloat16(vb);
                    float la = va - __bfloat162float(ha);
                    float lb = vb - __bfloat162float(hb);
                    hhi[p] = (unsigned)__bfloat16_as_ushort(ha)
                           | ((unsigned)__bfloat16_as_ushort(hb) << 16);
                    hlo[p] = pack_bf16(la, lb);
                }
            } else {
                #pragma unroll
                for (int p = 0; p < 16; p++) { hhi[p] = 0u; hlo[p] = 0u; }
            }
        }
        __syncthreads();

        // ---- phase 2: tensor MMA, warp-local ----
        const char* hhiB = smem + OFF_HHI;
        const char* hloB = smem + OFF_HLO;
        const char* whiB = smem + OFF_W2HI;
        const char* wloB = smem + OFF_W2LO;

        float mxf[4][4];
        #pragma unroll
        for (int nf = 0; nf < 4; nf++)
            #pragma unroll
            for (int c = 0; c < 4; c++) mxf[nf][c] = -3.402823466e38f;

        #pragma unroll 1
        for (int mtile = 0; mtile < TILE / 16; mtile++) {
            const int r0 = mtile * 16 + lq;      // rows this lane covers
            const int r1 = r0 + 8;

            float acc[4][4];
            #pragma unroll
            for (int nf = 0; nf < 4; nf++)
                #pragma unroll
                for (int c = 0; c < 4; c++) acc[nf][c] = 0.0f;

            #pragma unroll
            for (int ks = 0; ks < 4; ks++) {
                const int c0 = ks * 16 + 2 * lr;     // k col pair base (even)
                unsigned ah0 = *reinterpret_cast<const unsigned*>(hhiB + (r0 * RSTRIDE + c0) * 2);
                unsigned ah1 = *reinterpret_cast<const unsigned*>(hhiB + (r1 * RSTRIDE + c0) * 2);
                unsigned ah2 = *reinterpret_cast<const unsigned*>(hhiB + (r0 * RSTRIDE + c0 + 8) * 2);
                unsigned ah3 = *reinterpret_cast<const unsigned*>(hhiB + (r1 * RSTRIDE + c0 + 8) * 2);
                unsigned al0 = *reinterpret_cast<const unsigned*>(hloB + (r0 * RSTRIDE + c0) * 2);
                unsigned al1 = *reinterpret_cast<const unsigned*>(hloB + (r1 * RSTRIDE + c0) * 2);
                unsigned al2 = *reinterpret_cast<const unsigned*>(hloB + (r0 * RSTRIDE + c0 + 8) * 2);
                unsigned al3 = *reinterpret_cast<const unsigned*>(hloB + (r1 * RSTRIDE + c0 + 8) * 2);

                #pragma unroll
                for (int nf = 0; nf < 4; nf++) {
                    const int n = d0 + nf * 8 + lq;  // this lane's B column
                    unsigned bh0 = *reinterpret_cast<const unsigned*>(whiB + (n * RSTRIDE + c0) * 2);
                    unsigned bh1 = *reinterpret_cast<const unsigned*>(whiB + (n * RSTRIDE + c0 + 8) * 2);
                    unsigned bl0 = *reinterpret_cast<const unsigned*>(wloB + (n * RSTRIDE + c0) * 2);
                    unsigned bl1 = *reinterpret_cast<const unsigned*>(wloB + (n * RSTRIDE + c0 + 8) * 2);
                    mma_bf16(acc[nf], ah0, ah1, ah2, ah3, bh0, bh1);
                    mma_bf16(acc[nf], ah0, ah1, ah2, ah3, bl0, bl1);
                    mma_bf16(acc[nf], al0, al1, al2, al3, bh0, bh1);
                }
            }

            // fold with row masking (c0,c1 -> row r0; c2,c3 -> row r1)
            const bool v0 = (r0 < npts);
            const bool v1 = (r1 < npts);
            #pragma unroll
            for (int nf = 0; nf < 4; nf++) {
                if (v0) {
                    mxf[nf][0] = fmaxf(mxf[nf][0], acc[nf][0]);
                    mxf[nf][1] = fmaxf(mxf[nf][1], acc[nf][1]);
                }
                if (v1) {
                    mxf[nf][2] = fmaxf(mxf[nf][2], acc[nf][2]);
                    mxf[nf][3] = fmaxf(mxf[nf][3], acc[nf][3]);
                }
            }
        }

        // combine row-halves, butterfly over lanes with equal column (xor 4,8,16)
        float m0[4], m1[4];
        #pragma unroll
        for (int nf = 0; nf < 4; nf++) {
            m0[nf] = fmaxf(mxf[nf][0], mxf[nf][2]);   // col 2*lr
            m1[nf] = fmaxf(mxf[nf][1], mxf[nf][3]);   // col 2*lr+1
        }
        #pragma unroll
        for (int s = 4; s < 32; s <<= 1) {
            #pragma unroll
            for (int nf = 0; nf < 4; nf++) {
                m0[nf] = fmaxf(m0[nf], __shfl_xor_sync(0xffffffffu, m0[nf], s));
                m1[nf] = fmaxf(m1[nf], __shfl_xor_sync(0xffffffffu, m1[nf], s));
            }
        }
        if (lane < 4) {
            #pragma unroll
            for (int nf = 0; nf < 4; nf++) {
                int d = d0 + nf * 8 + 2 * lane;
                float va = m0[nf] + b2[kb * DD + d];
                float vb = m1[nf] + b2[kb * DD + d + 1];
                atomicMax(&g_maxu[b * DD + d],     flip_f32(va));
                atomicMax(&g_maxu[b * DD + d + 1], flip_f32(vb));
            }
        }
    }
}

// ---------------- K3: global MLP on per-batch max ----------------
__global__ __launch_bounds__(1024, 1)
void k3_head(const float* __restrict__ Wg1, const float* __restrict__ bg1,
             const float* __restrict__ Wg2, const float* __restrict__ bg2,
             float* __restrict__ out) {
    __shared__ float sg[DD];
    __shared__ float part[1024];
    __shared__ float shg[GHID];
    const int b   = blockIdx.x;
    const int tid = threadIdx.x;
    const int t   = tid & 127;     // output unit
    const int g   = tid >> 7;      // j-split group 0..7

    if (tid < DD) sg[tid] = unflip_f32(g_maxu[b * DD + tid]);
    __syncthreads();

    // layer 1: 256 -> 128, each thread covers 32 j's
    {
        float acc = 0.0f;
        const int j0 = g * 32;
        #pragma unroll 16
        for (int j = 0; j < 32; j++)
            acc = fmaf(sg[j0 + j], Wg1[(j0 + j) * GHID + t], acc);
        part[tid] = acc;
    }
    __syncthreads();
    if (tid < GHID) {
        float v = bg1[tid];
        #pragma unroll
        for (int gg = 0; gg < 8; gg++) v += part[tid + 128 * gg];
        shg[tid] = gelu_exact(v);
    }
    __syncthreads();

    // layer 2: 128 -> 128, each thread covers 16 j's
    {
        float acc = 0.0f;
        const int j0 = g * 16;
        #pragma unroll 16
        for (int j = 0; j < 16; j++)
            acc = fmaf(shg[j0 + j], Wg2[(j0 + j) * DOUT + t], acc);
        part[tid] = acc;
    }
    __syncthreads();
    if (tid < DOUT) {
        float v = bg2[tid];
        #pragma unroll
        for (int gg = 0; gg < 8; gg++) v += part[tid + 128 * gg];
        out[b * DOUT + tid] = v;
    }
}

// ---------------- launch ----------------
extern "C" void kernel_launch(void* const* d_in, const int* in_sizes, int n_in,
                              void* d_out, int out_size) {
    const float* x     = (const float*)d_in[0];
    const float* xlab  = (const float*)d_in[1];
    const float* W1    = (const float*)d_in[2];
    const float* b1    = (const float*)d_in[3];
    const float* W2    = (const float*)d_in[4];
    const float* b2    = (const float*)d_in[5];
    const float* Wg1   = (const float*)d_in[6];
    const float* bg1   = (const float*)d_in[7];
    const float* Wg2   = (const float*)d_in[8];
    const float* bg2   = (const float*)d_in[9];
    float* out = (float*)d_out;

    // opt-in to 110.5 KB dynamic smem for k2 (attribute set, not an allocation)
    cudaFuncSetAttribute(k2_main, cudaFuncAttributeMaxDynamicSharedMemorySize,
                         K2_SMEM);

    k0_init<<<(BB * DD + 255) / 256, 256>>>();
    k1_classify<<<(BB * NN) / 256, 256>>>(xlab);
    k2_main<<<PBLOCKS, 256, K2_SMEM>>>(x, W1, b1, W2, b2);
    k3_head<<<BB, 1024>>>(Wg1, bg1, Wg2, bg2, out);
}

// round 16
// speedup vs baseline: 1.0217x; 1.0217x over previous
#include <cuda_runtime.h>
#include <cuda_bf16.h>
#include <cstdint>

// Problem constants
#define BB   16
#define NN   8192
#define CIN  3
#define HID  64
#define DD   256
#define KK   4
#define GHID 128
#define DOUT 128
#define TILE 128
#define NT   (NN / TILE)            // 64 tiles
#define SLOTS (NT * BB)             // 1024 (tile,b) slots per branch
#define BLKS_PER_KB 74
#define PBLOCKS (BLKS_PER_KB * KK)  // 296 = 2 CTAs x 148 SMs

#define RSTRIDE 72                  // padded row stride in bf16 units (144 B)

// dynamic smem layout (bytes)
#define OFF_W2HI 0                      // [DD][RSTRIDE] bf16 = 36864
#define OFF_W2LO 36864                  // 36864
#define OFF_HHI  73728                  // [TILE][RSTRIDE] bf16 = 18432
#define OFF_HLO  92160                  // 18432
#define OFF_X0   110592                 // [TILE] float
#define OFF_X1   111104
#define OFF_X2   111616
#define OFF_W1   112128                 // [CIN*HID] float
#define OFF_B1   112896                 // [HID] float
#define K2_SMEM  113152                 // 110.5 KB -> 2 CTAs = 221 KB/SM

// ---------------- device scratch (static, no allocations) ----------------
__device__ int      g_cnt[BB * KK];
__device__ int      g_idx[BB * KK * NN];       // per (b,k) index lists
__device__ unsigned g_maxu[BB * DD];           // flipped-float max slots

// ---------------- helpers ----------------
__device__ __forceinline__ float gelu_exact(float x) {
    return 0.5f * x * (1.0f + erff(x * 0.7071067811865476f));
}

// Fast exact-GELU for small |v| (Taylor of erf, rel err < 1.3e-6 for |v|<=0.5)
__device__ __forceinline__ float gelu_fast(float v) {
    float s = v * v;
    if (s > 0.25f) {
        return 0.5f * v * (1.0f + erff(v * 0.7071067811865476f));
    }
    float p = fmaf(s, -1.0f / 336.0f, 1.0f / 40.0f);
    p = fmaf(s, p, -1.0f / 6.0f);
    p = fmaf(s, p, 1.0f);
    return fmaf(0.3989422804014327f * v * v, p, 0.5f * v);
}

__device__ __forceinline__ unsigned pack_bf16(float a, float b) {
    unsigned short ua = __bfloat16_as_ushort(__float2bfloat16(a));
    unsigned short ub = __bfloat16_as_ushort(__float2bfloat16(b));
    return (unsigned)ua | ((unsigned)ub << 16);
}

// m16n8k16 row.col bf16 MMA, fp32 accumulate (standard sm_80+ fragment layout)
__device__ __forceinline__ void mma_bf16(float* c,
                                         unsigned a0, unsigned a1,
                                         unsigned a2, unsigned a3,
                                         unsigned b0, unsigned b1) {
    asm volatile(
        "mma.sync.aligned.m16n8k16.row.col.f32.bf16.bf16.f32 "
        "{%0,%1,%2,%3}, {%4,%5,%6,%7}, {%8,%9}, {%0,%1,%2,%3};\n"
        : "+f"(c[0]), "+f"(c[1]), "+f"(c[2]), "+f"(c[3])
        : "r"(a0), "r"(a1), "r"(a2), "r"(a3), "r"(b0), "r"(b1));
}

__device__ __forceinline__ void ldsm_x4(unsigned& r0, unsigned& r1,
                                        unsigned& r2, unsigned& r3,
                                        unsigned addr) {
    asm volatile("ldmatrix.sync.aligned.m8n8.x4.shared.b16 {%0,%1,%2,%3}, [%4];"
                 : "=r"(r0), "=r"(r1), "=r"(r2), "=r"(r3) : "r"(addr));
}

// order-preserving float -> uint mapping (for exact atomic max)
__device__ __forceinline__ unsigned flip_f32(float f) {
    unsigned u = __float_as_uint(f);
    return (u & 0x80000000u) ? ~u : (u | 0x80000000u);
}
__device__ __forceinline__ float unflip_f32(unsigned e) {
    unsigned u = (e & 0x80000000u) ? (e ^ 0x80000000u) : ~e;
    return __uint_as_float(u);
}

// ---------------- K0: reset scratch ----------------
__global__ void k0_init() {
    int i = blockIdx.x * 256 + threadIdx.x;
    if (i < BB * KK) g_cnt[i] = 0;
    if (i < BB * DD) g_maxu[i] = 0u;   // below all finite flipped floats
}

// ---------------- K1: argmax classify + compaction ----------------
__global__ void k1_classify(const float* __restrict__ lab) {
    __shared__ int scnt[KK];
    __shared__ int sbase[KK];
    int t   = threadIdx.x;
    int gid = blockIdx.x * 256 + t;
    int b   = gid / NN;
    int n   = gid % NN;

    if (t < KK) scnt[t] = 0;
    __syncthreads();

    const float* lb = lab + (size_t)b * KK * NN + n;
    float l0 = lb[0], l1 = lb[NN], l2 = lb[2 * NN], l3 = lb[3 * NN];
    int k = 0; float best = l0;
    if (l1 > best) { best = l1; k = 1; }
    if (l2 > best) { best = l2; k = 2; }
    if (l3 > best) { best = l3; k = 3; }

    int pos = atomicAdd(&scnt[k], 1);
    __syncthreads();
    if (t < KK) sbase[t] = atomicAdd(&g_cnt[b * KK + t], scnt[t]);
    __syncthreads();
    g_idx[(b * KK + k) * NN + sbase[k] + pos] = n;
}

// ---------------- K2: persistent, branch-pinned, TENSOR phase 2 ----------------
// Identical to R15 except fragment loads use ldmatrix.x4:
//   per (mtile, kstep): 2 LDSM for A (hi/lo) + 4 LDSM for B (hi/lo x 2 k-halves,
//   each covering all 4 nf columns) = 6 LDSM instead of 24 scalar LDS.32.
__global__ __launch_bounds__(256, 2)
void k2_main(const float* __restrict__ x,
             const float* __restrict__ W1, const float* __restrict__ b1,
             const float* __restrict__ W2g, const float* __restrict__ b2) {
    extern __shared__ __align__(16) char smem[];
    __nv_bfloat16* w2hi = reinterpret_cast<__nv_bfloat16*>(smem + OFF_W2HI);
    __nv_bfloat16* w2lo = reinterpret_cast<__nv_bfloat16*>(smem + OFF_W2LO);
    float* sh_x0 = reinterpret_cast<float*>(smem + OFF_X0);
    float* sh_x1 = reinterpret_cast<float*>(smem + OFF_X1);
    float* sh_x2 = reinterpret_cast<float*>(smem + OFF_X2);
    float* sh_w1 = reinterpret_cast<float*>(smem + OFF_W1);
    float* sh_b1 = reinterpret_cast<float*>(smem + OFF_B1);

    const int t     = threadIdx.x;
    const int kb    = blockIdx.x & 3;
    const int slot0 = blockIdx.x >> 2;       // 0..73
    const int w     = t >> 5;                // warp 0..7
    const int lane  = t & 31;
    const int lq    = lane >> 2;             // 0..7 (row group / n col)
    const int lr    = lane & 3;              // 0..3 (k/col pair select)
    const int d0    = w * 32;

    // ---- once per block: W1/b1 + W2 split->bf16, transposed [d][k] ----
    {
        const int d = t;                     // 0..255
        #pragma unroll 8
        for (int k = 0; k < HID; k++) {
            float wv = W2g[((size_t)kb * HID + k) * DD + d];
            __nv_bfloat16 hi = __float2bfloat16(wv);
            float lo = wv - __bfloat162float(hi);
            w2hi[d * RSTRIDE + k] = hi;
            w2lo[d * RSTRIDE + k] = __float2bfloat16(lo);
        }
        if (t < CIN * HID) sh_w1[t] = W1[kb * CIN * HID + t];
        if (t < HID)       sh_b1[t] = b1[kb * HID + t];
    }
    __syncthreads();

    // shared-state-space base for ldmatrix
    const unsigned sbase = (unsigned)__cvta_generic_to_shared(smem);

    // per-lane ldmatrix offsets (in bf16 elements)
    const int mj        = lane >> 3;                       // matrix index 0..3
    const int a_off     = ((mj & 1) * 8 + (lane & 7)) * RSTRIDE + (mj >> 1) * 8;
    const int b_off     = (d0 + mj * 8 + (lane & 7)) * RSTRIDE;

    const unsigned aHiBase = sbase + OFF_HHI  + a_off * 2;
    const unsigned aLoBase = sbase + OFF_HLO  + a_off * 2;
    const unsigned bHiBase = sbase + OFF_W2HI + b_off * 2;
    const unsigned bLoBase = sbase + OFF_W2LO + b_off * 2;

    for (int it = slot0; it < SLOTS; it += BLKS_PER_KB) {
        const int tile = it >> 4;            // 0..63
        const int b    = it & 15;

        const int cnt   = g_cnt[b * KK + kb];
        const int start = tile * TILE;
        if (start >= cnt) continue;          // block-uniform branch
        const int npts = min(TILE, cnt - start);

        __syncthreads();   // previous item's phase-2 reads done before overwrite

        // direct gather: idx -> register -> x into smem (no idx staging)
        if (t < TILE && t < npts) {
            int n = g_idx[(b * KK + kb) * NN + start + t];
            const float* xb = x + (size_t)b * CIN * NN;
            sh_x0[t] = xb[n];
            sh_x1[t] = xb[NN + n];
            sh_x2[t] = xb[2 * NN + n];
        }
        __syncthreads();

        // ---- phase 1: pt = t&127, jhalf = t>>7 covers 32 j's; bf16 split
        {
            const int pt = t & 127;
            const int j0 = (t >> 7) * 32;
            unsigned* hhi = reinterpret_cast<unsigned*>(smem + OFF_HHI) + (pt * RSTRIDE + j0) / 2;
            unsigned* hlo = reinterpret_cast<unsigned*>(smem + OFF_HLO) + (pt * RSTRIDE + j0) / 2;
            if (pt < npts) {
                float x0 = sh_x0[pt], x1 = sh_x1[pt], x2 = sh_x2[pt];
                #pragma unroll
                for (int p = 0; p < 16; p++) {
                    int ja = j0 + 2 * p, jb = ja + 1;
                    float va = fmaf(x0, sh_w1[ja],
                               fmaf(x1, sh_w1[HID + ja],
                               fmaf(x2, sh_w1[2 * HID + ja], sh_b1[ja])));
                    float vb = fmaf(x0, sh_w1[jb],
                               fmaf(x1, sh_w1[HID + jb],
                               fmaf(x2, sh_w1[2 * HID + jb], sh_b1[jb])));
                    va = gelu_fast(va);
                    vb = gelu_fast(vb);
                    __nv_bfloat16 ha = __float2bfloat16(va);
                    __nv_bfloat16 hb = __float2bfloat16(vb);
                    float la = va - __bfloat162float(ha);
                    float lb = vb - __bfloat162float(hb);
                    hhi[p] = (unsigned)__bfloat16_as_ushort(ha)
                           | ((unsigned)__bfloat16_as_ushort(hb) << 16);
                    hlo[p] = pack_bf16(la, lb);
                }
            } else {
                #pragma unroll
                for (int p = 0; p < 16; p++) { hhi[p] = 0u; hlo[p] = 0u; }
            }
        }
        __syncthreads();

        // ---- phase 2: tensor MMA with ldmatrix fragment loads ----
        float mxf[4][4];
        #pragma unroll
        for (int nf = 0; nf < 4; nf++)
            #pragma unroll
            for (int c = 0; c < 4; c++) mxf[nf][c] = -3.402823466e38f;

        #pragma unroll 1
        for (int mtile = 0; mtile < TILE / 16; mtile++) {
            const int r0 = mtile * 16 + lq;      // rows this lane covers
            const int r1 = r0 + 8;
            const unsigned aHiM = aHiBase + (mtile * 16 * RSTRIDE) * 2;
            const unsigned aLoM = aLoBase + (mtile * 16 * RSTRIDE) * 2;

            float acc[4][4];
            #pragma unroll
            for (int nf = 0; nf < 4; nf++)
                #pragma unroll
                for (int c = 0; c < 4; c++) acc[nf][c] = 0.0f;

            #pragma unroll
            for (int ks = 0; ks < 4; ks++) {
                // A fragments (this lane's rows/cols per ldmatrix mapping)
                unsigned ah0, ah1, ah2, ah3, al0, al1, al2, al3;
                ldsm_x4(ah0, ah1, ah2, ah3, aHiM + (ks * 16) * 2);
                ldsm_x4(al0, al1, al2, al3, aLoM + (ks * 16) * 2);
                // B fragments: one x4 covers all 4 nf columns
                unsigned bh0[4], bh1[4], bl0[4], bl1[4];
                ldsm_x4(bh0[0], bh0[1], bh0[2], bh0[3], bHiBase + (ks * 16) * 2);
                ldsm_x4(bh1[0], bh1[1], bh1[2], bh1[3], bHiBase + (ks * 16 + 8) * 2);
                ldsm_x4(bl0[0], bl0[1], bl0[2], bl0[3], bLoBase + (ks * 16) * 2);
                ldsm_x4(bl1[0], bl1[1], bl1[2], bl1[3], bLoBase + (ks * 16 + 8) * 2);

                #pragma unroll
                for (int nf = 0; nf < 4; nf++) {
                    mma_bf16(acc[nf], ah0, ah1, ah2, ah3, bh0[nf], bh1[nf]);
                    mma_bf16(acc[nf], ah0, ah1, ah2, ah3, bl0[nf], bl1[nf]);
                    mma_bf16(acc[nf], al0, al1, al2, al3, bh0[nf], bh1[nf]);
                }
            }

            // fold with row masking (c0,c1 -> row r0; c2,c3 -> row r1)
            const bool v0 = (r0 < npts);
            const bool v1 = (r1 < npts);
            #pragma unroll
            for (int nf = 0; nf < 4; nf++) {
                if (v0) {
                    mxf[nf][0] = fmaxf(mxf[nf][0], acc[nf][0]);
                    mxf[nf][1] = fmaxf(mxf[nf][1], acc[nf][1]);
                }
                if (v1) {
                    mxf[nf][2] = fmaxf(mxf[nf][2], acc[nf][2]);
                    mxf[nf][3] = fmaxf(mxf[nf][3], acc[nf][3]);
                }
            }
        }

        // combine row-halves, butterfly over lanes with equal column (xor 4,8,16)
        float m0[4], m1[4];
        #pragma unroll
        for (int nf = 0; nf < 4; nf++) {
            m0[nf] = fmaxf(mxf[nf][0], mxf[nf][2]);   // col 2*lr
            m1[nf] = fmaxf(mxf[nf][1], mxf[nf][3]);   // col 2*lr+1
        }
        #pragma unroll
        for (int s = 4; s < 32; s <<= 1) {
            #pragma unroll
            for (int nf = 0; nf < 4; nf++) {
                m0[nf] = fmaxf(m0[nf], __shfl_xor_sync(0xffffffffu, m0[nf], s));
                m1[nf] = fmaxf(m1[nf], __shfl_xor_sync(0xffffffffu, m1[nf], s));
            }
        }
        if (lane < 4) {
            #pragma unroll
            for (int nf = 0; nf < 4; nf++) {
                int d = d0 + nf * 8 + 2 * lane;
                float va = m0[nf] + b2[kb * DD + d];
                float vb = m1[nf] + b2[kb * DD + d + 1];
                atomicMax(&g_maxu[b * DD + d],     flip_f32(va));
                atomicMax(&g_maxu[b * DD + d + 1], flip_f32(vb));
            }
        }
    }
}

// ---------------- K3: global MLP on per-batch max ----------------
__global__ __launch_bounds__(1024, 1)
void k3_head(const float* __restrict__ Wg1, const float* __restrict__ bg1,
             const float* __restrict__ Wg2, const float* __restrict__ bg2,
             float* __restrict__ out) {
    __shared__ float sg[DD];
    __shared__ float part[1024];
    __shared__ float shg[GHID];
    const int b   = blockIdx.x;
    const int tid = threadIdx.x;
    const int t   = tid & 127;     // output unit
    const int g   = tid >> 7;      // j-split group 0..7

    if (tid < DD) sg[tid] = unflip_f32(g_maxu[b * DD + tid]);
    __syncthreads();

    // layer 1: 256 -> 128, each thread covers 32 j's
    {
        float acc = 0.0f;
        const int j0 = g * 32;
        #pragma unroll 16
        for (int j = 0; j < 32; j++)
            acc = fmaf(sg[j0 + j], Wg1[(j0 + j) * GHID + t], acc);
        part[tid] = acc;
    }
    __syncthreads();
    if (tid < GHID) {
        float v = bg1[tid];
        #pragma unroll
        for (int gg = 0; gg < 8; gg++) v += part[tid + 128 * gg];
        shg[tid] = gelu_exact(v);
    }
    __syncthreads();

    // layer 2: 128 -> 128, each thread covers 16 j's
    {
        float acc = 0.0f;
        const int j0 = g * 16;
        #pragma unroll 16
        for (int j = 0; j < 16; j++)
            acc = fmaf(shg[j0 + j], Wg2[(j0 + j) * DOUT + t], acc);
        part[tid] = acc;
    }
    __syncthreads();
    if (tid < DOUT) {
        float v = bg2[tid];
        #pragma unroll
        for (int gg = 0; gg < 8; gg++) v += part[tid + 128 * gg];
        out[b * DOUT + tid] = v;
    }
}

// ---------------- launch ----------------
extern "C" void kernel_launch(void* const* d_in, const int* in_sizes, int n_in,
                              void* d_out, int out_size) {
    const float* x     = (const float*)d_in[0];
    const float* xlab  = (const float*)d_in[1];
    const float* W1    = (const float*)d_in[2];
    const float* b1    = (const float*)d_in[3];
    const float* W2    = (const float*)d_in[4];
    const float* b2    = (const float*)d_in[5];
    const float* Wg1   = (const float*)d_in[6];
    const float* bg1   = (const float*)d_in[7];
    const float* Wg2   = (const float*)d_in[8];
    const float* bg2   = (const float*)d_in[9];
    float* out = (float*)d_out;

    // opt-in to 110.5 KB dynamic smem for k2 (attribute set, not an allocation)
    cudaFuncSetAttribute(k2_main, cudaFuncAttributeMaxDynamicSharedMemorySize,
                         K2_SMEM);

    k0_init<<<(BB * DD + 255) / 256, 256>>>();
    k1_classify<<<(BB * NN) / 256, 256>>>(xlab);
    k2_main<<<PBLOCKS, 256, K2_SMEM>>>(x, W1, b1, W2, b2);
    k3_head<<<BB, 1024>>>(Wg1, bg1, Wg2, bg2, out);
}